// round 14
// baseline (speedup 1.0000x reference)
#include <cuda_runtime.h>
#include <cuda_bf16.h>
#include <cstdint>

#define NB 4
#define D0 64
#define C1 64
#define C2 128
#define DS 32
#define NCELL (NB*DS*DS*DS)   // 131072

// ---------------- scratch (device globals) ----------------------------------
__device__ float          g_m2  [NCELL];
__device__ __nv_bfloat16  g_h1hi[NCELL*C1];     // conv1 input hi
__device__ __nv_bfloat16  g_h1lo[NCELL*C1];     // conv1 input lo
__device__ __nv_bfloat16  g_xhi [NCELL*C1];     // skip input hi
__device__ __nv_bfloat16  g_xlo [NCELL*C1];     // skip input lo
__device__ __nv_bfloat16  g_c1hi[NCELL*C2];     // conv2 input hi
__device__ __nv_bfloat16  g_c1lo[NCELL*C2];     // conv2 input lo
__device__ unsigned char  g_wA1[27*1*32768];    // conv1 B tiles (hi+lo)
__device__ unsigned char  g_wA2[(27*2+1)*32768];// conv2 B tiles + skip tile (stage 54)
__device__ int            g_mask_mode;

// ---------------- helpers ----------------------------------------------------
__device__ __forceinline__ uint32_t smem_u32(const void* p){
    uint32_t a;
    asm("{ .reg .u64 t; cvta.to.shared.u64 t, %1; cvt.u32.u64 %0, t; }" : "=r"(a) : "l"(p));
    return a;
}
__device__ __forceinline__ void cpa16z(uint32_t dst, const void* src, bool ok){
    int sz = ok ? 16 : 0;
    asm volatile("cp.async.cg.shared.global [%0], [%1], 16, %2;" :: "r"(dst), "l"(src), "r"(sz));
}
__device__ __forceinline__ void cpa_commit(){ asm volatile("cp.async.commit_group;"); }

__device__ __forceinline__ void ldsm4(uint32_t* r, uint32_t addr){
    asm volatile("ldmatrix.sync.aligned.m8n8.x4.shared.b16 {%0,%1,%2,%3}, [%4];"
        : "=r"(r[0]), "=r"(r[1]), "=r"(r[2]), "=r"(r[3]) : "r"(addr));
}
__device__ __forceinline__ void mma16816(float* d, const uint32_t* a, const uint32_t* b){
    asm volatile("mma.sync.aligned.m16n8k16.row.col.f32.bf16.bf16.f32 "
        "{%0,%1,%2,%3}, {%4,%5,%6,%7}, {%8,%9}, {%0,%1,%2,%3};"
        : "+f"(d[0]), "+f"(d[1]), "+f"(d[2]), "+f"(d[3])
        : "r"(a[0]), "r"(a[1]), "r"(a[2]), "r"(a[3]), "r"(b[0]), "r"(b[1]));
}
__device__ __host__ __forceinline__ uint32_t swz(uint32_t row, uint32_t bytecol){
    uint32_t off = row*128u + bytecol;
    return off ^ ((off >> 3) & 0x70u);
}

// ---------------- mask dtype detection ---------------------------------------
__global__ void k_detect(const unsigned int* __restrict__ m, int nwords)
{
    if (threadIdx.x == 0 && blockIdx.x == 0) {
        int mode = 0;
        for (int i = 0; i < nwords; i++) {
            unsigned w = m[i];
            if (w == 0u) continue;
            if (w == 1u)               mode = 0;
            else if (w == 0x3F800000u) mode = 0;
            else                       mode = 2;
            break;
        }
        g_mask_mode = mode;
    }
}
__device__ __forceinline__ bool mask_at(const void* m, long v, int mode)
{
    if (mode == 2) return ((const unsigned char*)m)[v] != 0;
    return ((const unsigned int*)m)[v] != 0u;
}

// ---------------- weight prep: transpose + hi/lo split + smem layout ---------
__global__ void k_prep_w(const float* __restrict__ w, unsigned char* __restrict__ dst, int CIN)
{
    const int total = 27*CIN*128;
    for (int e = blockIdx.x*blockDim.x + threadIdx.x; e < total; e += gridDim.x*blockDim.x) {
        const int t   = e / (CIN*128);
        const int rem = e - t*(CIN*128);
        const int ci  = rem >> 7;
        const int co  = rem & 127;
        const float wv = w[e];
        const __nv_bfloat16 hi = __float2bfloat16(wv);
        const __nv_bfloat16 lo = __float2bfloat16(wv - __bfloat162float(hi));
        const int kc = ci >> 6, cil = ci & 63;
        const int stage = t*(CIN >> 6) + kc;
        const uint32_t off = swz((uint32_t)co, (uint32_t)cil*2u);
        unsigned char* base = dst + (long)stage*32768;
        *(__nv_bfloat16*)(base + off)         = hi;
        *(__nv_bfloat16*)(base + 16384 + off) = lo;
    }
}

// skip weight: wsk [64 ci][128 co] -> stage-54 tile of g_wA2
__global__ void k_prep_skipw(const float* __restrict__ wsk, unsigned char* __restrict__ dst)
{
    const int e = blockIdx.x*blockDim.x + threadIdx.x;
    if (e < 64*128) {
        const int ci = e >> 7;
        const int co = e & 127;
        const float wv = wsk[e];
        const __nv_bfloat16 hi = __float2bfloat16(wv);
        const __nv_bfloat16 lo = __float2bfloat16(wv - __bfloat162float(hi));
        const uint32_t off = swz((uint32_t)co, (uint32_t)ci*2u);
        *(__nv_bfloat16*)(dst + off)         = hi;
        *(__nv_bfloat16*)(dst + 16384 + off) = lo;
    }
}

// ---------------- K1: LN1+affine+SiLU+mask + 2x downsample -------------------
// 128 thr/cell; warp w handles subvoxels 2w, 2w+1 in its two half-warps.
// lane&15 = channel group (4 ch via float4); 4-round half-warp shfl reduction.
__global__ void __launch_bounds__(128)
k_ln_ds(const float* __restrict__ feats, const void* __restrict__ mask,
        const float* __restrict__ gamma, const float* __restrict__ beta)
{
    const int bid = blockIdx.x;
    const int dx = bid & 31, dy = (bid >> 5) & 31, dz = (bid >> 10) & 31, b = bid >> 15;
    const int tid  = threadIdx.x;
    const int lane = tid & 31;
    const int s    = ((tid >> 5) << 1) + (lane >> 4);   // subvoxel 0..7
    const int ch4  = lane & 15;                          // 4-channel group
    const int mode = g_mask_mode;

    __shared__ float sh_h[8*64];
    __shared__ float sh_x[8*64];
    __shared__ int   sh_c[8];

    const int z = 2*dz + (s >> 2);
    const int y = 2*dy + ((s >> 1) & 1);
    const int x = 2*dx + (s & 1);
    const long v = (((long)b*D0 + z)*D0 + y)*D0 + x;
    const bool act = mask_at(mask, v, mode);

    const float4 f = *(const float4*)(feats + v*C1 + ch4*4);
    float a = f.x + f.y + f.z + f.w;
    float q = f.x*f.x + f.y*f.y + f.z*f.z + f.w*f.w;
    #pragma unroll
    for (int o = 1; o < 16; o <<= 1) {
        a += __shfl_xor_sync(0xffffffffu, a, o);
        q += __shfl_xor_sync(0xffffffffu, q, o);
    }
    const float mu  = a * (1.f/64.f);
    const float var = q * (1.f/64.f) - mu*mu;
    const float rs  = rsqrtf(var + 1e-6f);

    const float4 g  = *(const float4*)(gamma + ch4*4);
    const float4 be = *(const float4*)(beta  + ch4*4);
    const float xv[4] = {f.x, f.y, f.z, f.w};
    const float gg[4] = {g.x, g.y, g.z, g.w};
    const float bb[4] = {be.x, be.y, be.z, be.w};
    float oh[4], ox[4];
    #pragma unroll
    for (int i = 0; i < 4; i++) {
        float hv = (xv[i] - mu)*rs*gg[i] + bb[i];
        hv = hv / (1.f + __expf(-hv));
        oh[i] = act ? hv    : 0.f;
        ox[i] = act ? xv[i] : 0.f;
    }
    *(float4*)(sh_h + s*64 + ch4*4) = *(const float4*)oh;
    *(float4*)(sh_x + s*64 + ch4*4) = *(const float4*)ox;
    if (ch4 == 0) sh_c[s] = act ? 1 : 0;
    __syncthreads();

    if (tid < 64) {
        float hs = 0.f, xs = 0.f;
        int cnt = 0;
        #pragma unroll
        for (int k = 0; k < 8; k++) {
            hs += sh_h[k*64 + tid];
            xs += sh_x[k*64 + tid];
            cnt += sh_c[k];
        }
        const float inv = 1.f / (float)max(cnt, 1);
        const float hv = hs * inv;
        const float xm = xs * inv;
        const __nv_bfloat16 hhi = __float2bfloat16(hv);
        const __nv_bfloat16 hlo = __float2bfloat16(hv - __bfloat162float(hhi));
        const __nv_bfloat16 xhi = __float2bfloat16(xm);
        const __nv_bfloat16 xlo = __float2bfloat16(xm - __bfloat162float(xhi));
        g_h1hi[(long)bid*C1 + tid] = hhi;
        g_h1lo[(long)bid*C1 + tid] = hlo;
        g_xhi [(long)bid*C1 + tid] = xhi;
        g_xlo [(long)bid*C1 + tid] = xlo;
        if (tid == 0) g_m2[bid] = (cnt > 0) ? 1.f : 0.f;
    }
}

// ---------------- conv via mma.sync (split-bf16 3-term) ----------------------
// Block 256 thr / 8 warps. Tile: 128 voxels (4 dy rows x 32 x) x 128 cout.
// Triple-buffered, one barrier per stage. Z-boundary stages skipped entirely
// (their A tiles would be all-zero; acc starts at 0 so skipping is exact).
template<int CIN, bool FUSE_LN, bool HAS_SKIP>
__global__ void __launch_bounds__(256, 1)
k_convmma(const __nv_bfloat16* __restrict__ inhi, const __nv_bfloat16* __restrict__ inlo,
          const __nv_bfloat16* __restrict__ skhi, const __nv_bfloat16* __restrict__ sklo,
          const unsigned char* __restrict__ wA, const float* __restrict__ bias,
          const float* __restrict__ bias2, const float* __restrict__ m2,
          float* __restrict__ outf,
          __nv_bfloat16* __restrict__ outhi, __nv_bfloat16* __restrict__ outlo)
{
    constexpr int NKC = CIN / 64;
    constexpr int NS  = 27 * NKC;

    extern __shared__ char smraw[];
    const uint32_t sb0 = smem_u32(smraw);
    const uint32_t BUF = (sb0 + 1023) & ~1023u;
    float* s_red = (float*)(smraw + (BUF - sb0));

    const int tid  = threadIdx.x;
    const int lane = tid & 31;
    const int w    = tid >> 5;
    const int wm   = w >> 1;          // 0..3
    const int wn   = w & 1;           // 0..1
    const int dy0  = blockIdx.x * 4;
    const int dz   = blockIdx.y;
    const int b    = blockIdx.z;

    // z-boundary stage range: skip kd=0 stages at dz==0, kd=2 at dz==DS-1
    const int s_begin = (dz == 0)    ? 9*NKC  : 0;
    const int s_endc  = (dz == DS-1) ? 18*NKC : NS;
    const int nconv   = s_endc - s_begin;
    const int NT      = nconv + (HAS_SKIP ? 1 : 0);

    float acc[2][8][4];
    #pragma unroll
    for (int mf = 0; mf < 2; mf++)
        #pragma unroll
        for (int nf = 0; nf < 8; nf++)
            #pragma unroll
            for (int k = 0; k < 4; k++) acc[mf][nf][k] = 0.f;

    // ---- stage copier (takes logical index i in [0,NT)) ----
    auto stage_copy = [&](int i, int p){
        const int s = (i < nconv) ? (s_begin + i) : NS;
        const uint32_t base = BUF + (uint32_t)p * 65536u;
        if (HAS_SKIP && s == NS) {
            #pragma unroll
            for (int it = 0; it < 16; it++) {
                const int flat = tid + it*256;
                if (flat < 2048) {
                    const int half = flat >> 10;
                    const int f    = flat & 1023;
                    const int vox  = f >> 3;
                    const int seg  = f & 7;
                    const long cell = (((long)b*DS + dz)*DS + dy0 + (vox >> 5))*DS + (vox & 31);
                    const __nv_bfloat16* src =
                        (half ? sklo : skhi) + cell*C1 + seg*8;
                    cpa16z(base + (uint32_t)half*16384u + swz((uint32_t)vox, (uint32_t)seg*16u),
                           src, true);
                } else {
                    const int f = flat - 2048;
                    cpa16z(base + 32768u + (uint32_t)f*16u,
                           wA + (long)s*32768 + (long)f*16, true);
                }
            }
            cpa_commit();
            return;
        }
        const int t  = s / NKC;
        const int kc = s - t*NKC;
        const int kd = t / 9;
        const int r9 = t - kd*9;
        const int kh = r9 / 3;
        const int kw = r9 - kh*3;
        const int z  = dz + kd - 1;   // in range by construction of [s_begin, s_endc)
        #pragma unroll
        for (int it = 0; it < 16; it++) {
            const int flat = tid + it*256;           // 0..4095 (16B units)
            if (flat < 2048) {                       // A input tiles (hi, lo)
                const int half = flat >> 10;
                const int f    = flat & 1023;
                const int vox  = f >> 3;
                const int seg  = f & 7;
                const int r    = vox >> 5;
                const int x    = vox & 31;
                const int y    = dy0 + r + kh - 1;
                const int xx   = x + kw - 1;
                const bool ok  = ((unsigned)y < DS) && ((unsigned)xx < DS);
                const long cell = ok ? ((((long)b*DS + z)*DS + y)*DS + xx) : 0;
                const __nv_bfloat16* src =
                    (half ? inlo : inhi) + cell*CIN + kc*64 + seg*8;
                cpa16z(base + (uint32_t)half*16384u + swz((uint32_t)vox, (uint32_t)seg*16u),
                       src, ok);
            } else {                                  // B weight tiles
                const int f = flat - 2048;
                cpa16z(base + 32768u + (uint32_t)f*16u,
                       wA + (long)s*32768 + (long)f*16, true);
            }
        }
        cpa_commit();
    };

    stage_copy(0, 0);
    if (NT > 1) stage_copy(1, 1);

    int p = 0;
    for (int i = 0; i < NT; i++) {
        if (i < NT - 1) asm volatile("cp.async.wait_group 1;");
        else            asm volatile("cp.async.wait_group 0;");
        __syncthreads();

        if (i + 2 < NT) {
            int p2 = p + 2; if (p2 >= 3) p2 -= 3;
            stage_copy(i + 2, p2);
        }

        const uint32_t Ab = BUF + (uint32_t)p*65536u;
        const uint32_t Bb = Ab + 32768u;

        #pragma unroll
        for (int ks = 0; ks < 4; ks++) {
            const uint32_t colb = (uint32_t)(ks*16 + ((lane >> 4) & 1)*8) * 2u;
            uint32_t a_hi[2][4], a_lo[2][4];
            #pragma unroll
            for (int mf = 0; mf < 2; mf++) {
                const uint32_t row = (uint32_t)(wm*32 + mf*16 + (lane & 15));
                const uint32_t ad = Ab + swz(row, colb);
                ldsm4(a_hi[mf], ad);
                ldsm4(a_lo[mf], ad + 16384u);
            }
            uint32_t b_hi[8][2], b_lo[8][2];
            #pragma unroll
            for (int nf2 = 0; nf2 < 4; nf2++) {
                const uint32_t row = (uint32_t)(wn*64 + nf2*16 + (lane & 15));
                const uint32_t ad = Bb + swz(row, colb);
                uint32_t r4[4];
                ldsm4(r4, ad);
                b_hi[nf2*2][0] = r4[0]; b_hi[nf2*2+1][0] = r4[1];
                b_hi[nf2*2][1] = r4[2]; b_hi[nf2*2+1][1] = r4[3];
                ldsm4(r4, ad + 16384u);
                b_lo[nf2*2][0] = r4[0]; b_lo[nf2*2+1][0] = r4[1];
                b_lo[nf2*2][1] = r4[2]; b_lo[nf2*2+1][1] = r4[3];
            }
            // term-major: 16 independent accs per pass -> no RAW chains
            #pragma unroll
            for (int mf = 0; mf < 2; mf++)
                #pragma unroll
                for (int nf = 0; nf < 8; nf++)
                    mma16816(acc[mf][nf], a_hi[mf], b_hi[nf]);
            #pragma unroll
            for (int mf = 0; mf < 2; mf++)
                #pragma unroll
                for (int nf = 0; nf < 8; nf++)
                    mma16816(acc[mf][nf], a_hi[mf], b_lo[nf]);
            #pragma unroll
            for (int mf = 0; mf < 2; mf++)
                #pragma unroll
                for (int nf = 0; nf < 8; nf++)
                    mma16816(acc[mf][nf], a_lo[mf], b_hi[nf]);
        }
        p++; if (p == 3) p = 0;
    }
    __syncthreads();

    // ---- epilogue ----
    const int qr = lane >> 2;
    const int qc = lane & 3;

    #pragma unroll
    for (int mf = 0; mf < 2; mf++) {
        const int vox_lo = wm*32 + mf*16 + qr;
        const int vox_hi = vox_lo + 8;
        const long cell_lo = (((long)b*DS + dz)*DS + dy0 + (vox_lo >> 5))*DS + (vox_lo & 31);
        const long cell_hi = (((long)b*DS + dz)*DS + dy0 + (vox_hi >> 5))*DS + (vox_hi & 31);
        const float m_lo = m2[cell_lo];
        const float m_hi = m2[cell_hi];
        #pragma unroll
        for (int nf = 0; nf < 8; nf++) {
            const int co = wn*64 + nf*8 + qc*2;
            float b0 = bias[co], b1 = bias[co + 1];
            if (HAS_SKIP) { b0 += bias2[co]; b1 += bias2[co + 1]; }
            acc[mf][nf][0] = (acc[mf][nf][0] + b0) * m_lo;
            acc[mf][nf][1] = (acc[mf][nf][1] + b1) * m_lo;
            acc[mf][nf][2] = (acc[mf][nf][2] + b0) * m_hi;
            acc[mf][nf][3] = (acc[mf][nf][3] + b1) * m_hi;
        }
    }

    if (FUSE_LN) {
        float* ps = s_red;            // [128 vox][2 wn]
        float* qs = s_red + 256;
        #pragma unroll
        for (int mf = 0; mf < 2; mf++) {
            float S_lo = 0.f, Q_lo = 0.f, S_hi = 0.f, Q_hi = 0.f;
            #pragma unroll
            for (int nf = 0; nf < 8; nf++) {
                S_lo += acc[mf][nf][0] + acc[mf][nf][1];
                Q_lo += acc[mf][nf][0]*acc[mf][nf][0] + acc[mf][nf][1]*acc[mf][nf][1];
                S_hi += acc[mf][nf][2] + acc[mf][nf][3];
                Q_hi += acc[mf][nf][2]*acc[mf][nf][2] + acc[mf][nf][3]*acc[mf][nf][3];
            }
            #pragma unroll
            for (int o = 1; o < 4; o <<= 1) {
                S_lo += __shfl_xor_sync(0xffffffffu, S_lo, o);
                Q_lo += __shfl_xor_sync(0xffffffffu, Q_lo, o);
                S_hi += __shfl_xor_sync(0xffffffffu, S_hi, o);
                Q_hi += __shfl_xor_sync(0xffffffffu, Q_hi, o);
            }
            if (qc == 0) {
                const int vox_lo = wm*32 + mf*16 + qr;
                ps[vox_lo*2 + wn] = S_lo;  qs[vox_lo*2 + wn] = Q_lo;
                ps[(vox_lo + 8)*2 + wn] = S_hi;  qs[(vox_lo + 8)*2 + wn] = Q_hi;
            }
        }
        __syncthreads();
        #pragma unroll
        for (int mf = 0; mf < 2; mf++) {
            #pragma unroll
            for (int half = 0; half < 2; half++) {
                const int vox = wm*32 + mf*16 + qr + half*8;
                const long cell = (((long)b*DS + dz)*DS + dy0 + (vox >> 5))*DS + (vox & 31);
                const float m = m2[cell];
                const float S = ps[vox*2] + ps[vox*2 + 1];
                const float Q = qs[vox*2] + qs[vox*2 + 1];
                const float mu  = S * (1.f/128.f);
                const float var = Q * (1.f/128.f) - mu*mu;
                const float rsv = rsqrtf(var + 1e-6f);
                #pragma unroll
                for (int nf = 0; nf < 8; nf++) {
                    const int co = wn*64 + nf*8 + qc*2;
                    __nv_bfloat162 vh, vl;
                    #pragma unroll
                    for (int e = 0; e < 2; e++) {
                        const float lnv = (acc[mf][nf][half*2 + e] - mu) * rsv;
                        const float sil = (lnv / (1.f + __expf(-lnv))) * m;
                        const __nv_bfloat16 hi = __float2bfloat16(sil);
                        const __nv_bfloat16 lo = __float2bfloat16(sil - __bfloat162float(hi));
                        if (e == 0) { vh.x = hi; vl.x = lo; } else { vh.y = hi; vl.y = lo; }
                    }
                    *(__nv_bfloat162*)(outhi + cell*C2 + co) = vh;
                    *(__nv_bfloat162*)(outlo + cell*C2 + co) = vl;
                }
            }
        }
    } else {
        #pragma unroll
        for (int mf = 0; mf < 2; mf++) {
            #pragma unroll
            for (int half = 0; half < 2; half++) {
                const int vox = wm*32 + mf*16 + qr + half*8;
                const long cell = (((long)b*DS + dz)*DS + dy0 + (vox >> 5))*DS + (vox & 31);
                #pragma unroll
                for (int nf = 0; nf < 8; nf++) {
                    const int co = wn*64 + nf*8 + qc*2;
                    float2 v;
                    v.x = acc[mf][nf][half*2];
                    v.y = acc[mf][nf][half*2 + 1];
                    *(float2*)(outf + cell*C2 + co) = v;
                }
            }
        }
    }
}

// ---------------- launch ------------------------------------------------------
extern "C" void kernel_launch(void* const* d_in, const int* in_sizes, int n_in,
                              void* d_out, int out_size)
{
    const float* feats = (const float*)d_in[0];
    const void*  mask  = d_in[1];
    const float* gamma1= (const float*)d_in[2];
    const float* beta1 = (const float*)d_in[3];
    const float* w1    = (const float*)d_in[4];
    const float* b1    = (const float*)d_in[5];
    const float* w2    = (const float*)d_in[6];
    const float* b2    = (const float*)d_in[7];
    const float* wsk   = (const float*)d_in[8];
    const float* bsk   = (const float*)d_in[9];
    float* out = (float*)d_out;

    float *p_m2;
    __nv_bfloat16 *p_h1hi, *p_h1lo, *p_xhi, *p_xlo, *p_c1hi, *p_c1lo;
    unsigned char *p_wA1, *p_wA2;
    cudaGetSymbolAddress((void**)&p_m2,   g_m2);
    cudaGetSymbolAddress((void**)&p_h1hi, g_h1hi);
    cudaGetSymbolAddress((void**)&p_h1lo, g_h1lo);
    cudaGetSymbolAddress((void**)&p_xhi,  g_xhi);
    cudaGetSymbolAddress((void**)&p_xlo,  g_xlo);
    cudaGetSymbolAddress((void**)&p_c1hi, g_c1hi);
    cudaGetSymbolAddress((void**)&p_c1lo, g_c1lo);
    cudaGetSymbolAddress((void**)&p_wA1,  g_wA1);
    cudaGetSymbolAddress((void**)&p_wA2,  g_wA2);

    k_detect<<<1, 32>>>((const unsigned int*)mask, in_sizes[1] / 4);
    k_prep_w<<<432, 512>>>(w1, p_wA1, C1);
    k_prep_w<<<864, 512>>>(w2, p_wA2, C2);
    k_prep_skipw<<<16, 512>>>(wsk, p_wA2 + (long)54*32768);
    k_ln_ds<<<NCELL, 128>>>(feats, mask, gamma1, beta1);

    const size_t SMEMSZ = 1024 + 3*65536;             // align pad + 3 stage buffers
    dim3 gC(DS/4, DS, NB);                             // (dy strip, dz, b) = (8,32,4)

    cudaFuncSetAttribute(k_convmma<C1, true, false>,
                         cudaFuncAttributeMaxDynamicSharedMemorySize, (int)SMEMSZ);
    k_convmma<C1, true, false><<<gC, 256, SMEMSZ>>>(p_h1hi, p_h1lo, nullptr, nullptr,
                                                    p_wA1, b1, nullptr, p_m2,
                                                    nullptr, p_c1hi, p_c1lo);

    cudaFuncSetAttribute(k_convmma<C2, false, true>,
                         cudaFuncAttributeMaxDynamicSharedMemorySize, (int)SMEMSZ);
    k_convmma<C2, false, true><<<gC, 256, SMEMSZ>>>(p_c1hi, p_c1lo, p_xhi, p_xlo,
                                                    p_wA2, b2, bsk, p_m2,
                                                    out, nullptr, nullptr);
}

// round 15
// speedup vs baseline: 1.5510x; 1.5510x over previous
#include <cuda_runtime.h>
#include <cuda_bf16.h>
#include <cstdint>

#define NB 4
#define D0 64
#define C1 64
#define C2 128
#define DS 32
#define NCELL (NB*DS*DS*DS)   // 131072

// ---------------- scratch (device globals) ----------------------------------
__device__ float          g_m2  [NCELL];
__device__ __nv_bfloat16  g_h1hi[NCELL*C1];     // conv1 input hi
__device__ __nv_bfloat16  g_h1lo[NCELL*C1];     // conv1 input lo
__device__ __nv_bfloat16  g_xhi [NCELL*C1];     // skip input hi
__device__ __nv_bfloat16  g_xlo [NCELL*C1];     // skip input lo
__device__ __nv_bfloat16  g_c1hi[NCELL*C2];     // conv2 input hi
__device__ __nv_bfloat16  g_c1lo[NCELL*C2];     // conv2 input lo
__device__ unsigned char  g_wA1[27*1*32768];    // conv1 B tiles (hi+lo)
__device__ unsigned char  g_wA2[(27*2+1)*32768];// conv2 B tiles + skip tile (stage 54)
__device__ int            g_mask_mode;

// ---------------- helpers ----------------------------------------------------
__device__ __forceinline__ uint32_t smem_u32(const void* p){
    uint32_t a;
    asm("{ .reg .u64 t; cvta.to.shared.u64 t, %1; cvt.u32.u64 %0, t; }" : "=r"(a) : "l"(p));
    return a;
}
__device__ __forceinline__ void cpa16z(uint32_t dst, const void* src, bool ok){
    int sz = ok ? 16 : 0;
    asm volatile("cp.async.cg.shared.global [%0], [%1], 16, %2;" :: "r"(dst), "l"(src), "r"(sz));
}
__device__ __forceinline__ void cpa_commit(){ asm volatile("cp.async.commit_group;"); }

__device__ __forceinline__ void ldsm4(uint32_t* r, uint32_t addr){
    asm volatile("ldmatrix.sync.aligned.m8n8.x4.shared.b16 {%0,%1,%2,%3}, [%4];"
        : "=r"(r[0]), "=r"(r[1]), "=r"(r[2]), "=r"(r[3]) : "r"(addr));
}
__device__ __forceinline__ void mma16816(float* d, const uint32_t* a, const uint32_t* b){
    asm volatile("mma.sync.aligned.m16n8k16.row.col.f32.bf16.bf16.f32 "
        "{%0,%1,%2,%3}, {%4,%5,%6,%7}, {%8,%9}, {%0,%1,%2,%3};"
        : "+f"(d[0]), "+f"(d[1]), "+f"(d[2]), "+f"(d[3])
        : "r"(a[0]), "r"(a[1]), "r"(a[2]), "r"(a[3]), "r"(b[0]), "r"(b[1]));
}
__device__ __host__ __forceinline__ uint32_t swz(uint32_t row, uint32_t bytecol){
    uint32_t off = row*128u + bytecol;
    return off ^ ((off >> 3) & 0x70u);
}

// ---------------- mask dtype detection ---------------------------------------
__global__ void k_detect(const unsigned int* __restrict__ m, int nwords)
{
    if (threadIdx.x == 0 && blockIdx.x == 0) {
        int mode = 0;
        for (int i = 0; i < nwords; i++) {
            unsigned w = m[i];
            if (w == 0u) continue;
            if (w == 1u)               mode = 0;
            else if (w == 0x3F800000u) mode = 0;
            else                       mode = 2;
            break;
        }
        g_mask_mode = mode;
    }
}
__device__ __forceinline__ bool mask_at(const void* m, long v, int mode)
{
    if (mode == 2) return ((const unsigned char*)m)[v] != 0;
    return ((const unsigned int*)m)[v] != 0u;
}

// ---------------- weight prep: transpose + hi/lo split + smem layout ---------
__global__ void k_prep_w(const float* __restrict__ w, unsigned char* __restrict__ dst, int CIN)
{
    const int total = 27*CIN*128;
    for (int e = blockIdx.x*blockDim.x + threadIdx.x; e < total; e += gridDim.x*blockDim.x) {
        const int t   = e / (CIN*128);
        const int rem = e - t*(CIN*128);
        const int ci  = rem >> 7;
        const int co  = rem & 127;
        const float wv = w[e];
        const __nv_bfloat16 hi = __float2bfloat16(wv);
        const __nv_bfloat16 lo = __float2bfloat16(wv - __bfloat162float(hi));
        const int kc = ci >> 6, cil = ci & 63;
        const int stage = t*(CIN >> 6) + kc;
        const uint32_t off = swz((uint32_t)co, (uint32_t)cil*2u);
        unsigned char* base = dst + (long)stage*32768;
        *(__nv_bfloat16*)(base + off)         = hi;
        *(__nv_bfloat16*)(base + 16384 + off) = lo;
    }
}

// skip weight: wsk [64 ci][128 co] -> stage-54 tile of g_wA2
__global__ void k_prep_skipw(const float* __restrict__ wsk, unsigned char* __restrict__ dst)
{
    const int e = blockIdx.x*blockDim.x + threadIdx.x;
    if (e < 64*128) {
        const int ci = e >> 7;
        const int co = e & 127;
        const float wv = wsk[e];
        const __nv_bfloat16 hi = __float2bfloat16(wv);
        const __nv_bfloat16 lo = __float2bfloat16(wv - __bfloat162float(hi));
        const uint32_t off = swz((uint32_t)co, (uint32_t)ci*2u);
        *(__nv_bfloat16*)(dst + off)         = hi;
        *(__nv_bfloat16*)(dst + 16384 + off) = lo;
    }
}

// ---------------- K1: LN1+affine+SiLU+mask + 2x downsample -------------------
// 128 thr/cell; warp w handles subvoxels 2w, 2w+1 in its two half-warps.
// lane&15 = channel group (4 ch via float4); 4-round half-warp shfl reduction.
__global__ void __launch_bounds__(128)
k_ln_ds(const float* __restrict__ feats, const void* __restrict__ mask,
        const float* __restrict__ gamma, const float* __restrict__ beta)
{
    const int bid = blockIdx.x;
    const int dx = bid & 31, dy = (bid >> 5) & 31, dz = (bid >> 10) & 31, b = bid >> 15;
    const int tid  = threadIdx.x;
    const int lane = tid & 31;
    const int s    = ((tid >> 5) << 1) + (lane >> 4);   // subvoxel 0..7
    const int ch4  = lane & 15;                          // 4-channel group
    const int mode = g_mask_mode;

    __shared__ float sh_h[8*64];
    __shared__ float sh_x[8*64];
    __shared__ int   sh_c[8];

    const int z = 2*dz + (s >> 2);
    const int y = 2*dy + ((s >> 1) & 1);
    const int x = 2*dx + (s & 1);
    const long v = (((long)b*D0 + z)*D0 + y)*D0 + x;
    const bool act = mask_at(mask, v, mode);

    const float4 f = *(const float4*)(feats + v*C1 + ch4*4);
    float a = f.x + f.y + f.z + f.w;
    float q = f.x*f.x + f.y*f.y + f.z*f.z + f.w*f.w;
    #pragma unroll
    for (int o = 1; o < 16; o <<= 1) {
        a += __shfl_xor_sync(0xffffffffu, a, o);
        q += __shfl_xor_sync(0xffffffffu, q, o);
    }
    const float mu  = a * (1.f/64.f);
    const float var = q * (1.f/64.f) - mu*mu;
    const float rs  = rsqrtf(var + 1e-6f);

    const float4 g  = *(const float4*)(gamma + ch4*4);
    const float4 be = *(const float4*)(beta  + ch4*4);
    const float xv[4] = {f.x, f.y, f.z, f.w};
    const float gg[4] = {g.x, g.y, g.z, g.w};
    const float bb[4] = {be.x, be.y, be.z, be.w};
    float oh[4], ox[4];
    #pragma unroll
    for (int i = 0; i < 4; i++) {
        float hv = (xv[i] - mu)*rs*gg[i] + bb[i];
        hv = hv / (1.f + __expf(-hv));
        oh[i] = act ? hv    : 0.f;
        ox[i] = act ? xv[i] : 0.f;
    }
    *(float4*)(sh_h + s*64 + ch4*4) = *(const float4*)oh;
    *(float4*)(sh_x + s*64 + ch4*4) = *(const float4*)ox;
    if (ch4 == 0) sh_c[s] = act ? 1 : 0;
    __syncthreads();

    if (tid < 64) {
        float hs = 0.f, xs = 0.f;
        int cnt = 0;
        #pragma unroll
        for (int k = 0; k < 8; k++) {
            hs += sh_h[k*64 + tid];
            xs += sh_x[k*64 + tid];
            cnt += sh_c[k];
        }
        const float inv = 1.f / (float)max(cnt, 1);
        const float hv = hs * inv;
        const float xm = xs * inv;
        const __nv_bfloat16 hhi = __float2bfloat16(hv);
        const __nv_bfloat16 hlo = __float2bfloat16(hv - __bfloat162float(hhi));
        const __nv_bfloat16 xhi = __float2bfloat16(xm);
        const __nv_bfloat16 xlo = __float2bfloat16(xm - __bfloat162float(xhi));
        g_h1hi[(long)bid*C1 + tid] = hhi;
        g_h1lo[(long)bid*C1 + tid] = hlo;
        g_xhi [(long)bid*C1 + tid] = xhi;
        g_xlo [(long)bid*C1 + tid] = xlo;
        if (tid == 0) g_m2[bid] = (cnt > 0) ? 1.f : 0.f;
    }
}

// ---------------- conv via mma.sync (split-bf16 3-term) ----------------------
// Block 256 thr / 8 warps. Tile: 128 voxels (4 dy rows x 32 x) x 128 cout.
// Triple-buffered, one barrier per stage. Z-boundary stages skipped entirely
// (their A tiles would be all-zero; acc starts at 0 so skipping is exact).
template<int CIN, bool FUSE_LN, bool HAS_SKIP>
__global__ void __launch_bounds__(256, 1)
k_convmma(const __nv_bfloat16* __restrict__ inhi, const __nv_bfloat16* __restrict__ inlo,
          const __nv_bfloat16* __restrict__ skhi, const __nv_bfloat16* __restrict__ sklo,
          const unsigned char* __restrict__ wA, const float* __restrict__ bias,
          const float* __restrict__ bias2, const float* __restrict__ m2,
          float* __restrict__ outf,
          __nv_bfloat16* __restrict__ outhi, __nv_bfloat16* __restrict__ outlo)
{
    constexpr int NKC = CIN / 64;
    constexpr int NS  = 27 * NKC;

    extern __shared__ char smraw[];
    const uint32_t sb0 = smem_u32(smraw);
    const uint32_t BUF = (sb0 + 1023) & ~1023u;
    float* s_red = (float*)(smraw + (BUF - sb0));

    const int tid  = threadIdx.x;
    const int lane = tid & 31;
    const int w    = tid >> 5;
    const int wm   = w >> 1;          // 0..3
    const int wn   = w & 1;           // 0..1
    const int dy0  = blockIdx.x * 4;
    const int dz   = blockIdx.y;
    const int b    = blockIdx.z;

    // z-boundary stage range: skip kd=0 stages at dz==0, kd=2 at dz==DS-1
    const int s_begin = (dz == 0)    ? 9*NKC  : 0;
    const int s_endc  = (dz == DS-1) ? 18*NKC : NS;
    const int nconv   = s_endc - s_begin;
    const int NT      = nconv + (HAS_SKIP ? 1 : 0);

    float acc[2][8][4];
    #pragma unroll
    for (int mf = 0; mf < 2; mf++)
        #pragma unroll
        for (int nf = 0; nf < 8; nf++)
            #pragma unroll
            for (int k = 0; k < 4; k++) acc[mf][nf][k] = 0.f;

    // ---- stage copier (takes logical index i in [0,NT)) ----
    auto stage_copy = [&](int i, int p){
        const int s = (i < nconv) ? (s_begin + i) : NS;
        const uint32_t base = BUF + (uint32_t)p * 65536u;
        if (HAS_SKIP && s == NS) {
            #pragma unroll
            for (int it = 0; it < 16; it++) {
                const int flat = tid + it*256;
                if (flat < 2048) {
                    const int half = flat >> 10;
                    const int f    = flat & 1023;
                    const int vox  = f >> 3;
                    const int seg  = f & 7;
                    const long cell = (((long)b*DS + dz)*DS + dy0 + (vox >> 5))*DS + (vox & 31);
                    const __nv_bfloat16* src =
                        (half ? sklo : skhi) + cell*C1 + seg*8;
                    cpa16z(base + (uint32_t)half*16384u + swz((uint32_t)vox, (uint32_t)seg*16u),
                           src, true);
                } else {
                    const int f = flat - 2048;
                    cpa16z(base + 32768u + (uint32_t)f*16u,
                           wA + (long)s*32768 + (long)f*16, true);
                }
            }
            cpa_commit();
            return;
        }
        const int t  = s / NKC;
        const int kc = s - t*NKC;
        const int kd = t / 9;
        const int r9 = t - kd*9;
        const int kh = r9 / 3;
        const int kw = r9 - kh*3;
        const int z  = dz + kd - 1;   // in range by construction of [s_begin, s_endc)
        #pragma unroll
        for (int it = 0; it < 16; it++) {
            const int flat = tid + it*256;           // 0..4095 (16B units)
            if (flat < 2048) {                       // A input tiles (hi, lo)
                const int half = flat >> 10;
                const int f    = flat & 1023;
                const int vox  = f >> 3;
                const int seg  = f & 7;
                const int r    = vox >> 5;
                const int x    = vox & 31;
                const int y    = dy0 + r + kh - 1;
                const int xx   = x + kw - 1;
                const bool ok  = ((unsigned)y < DS) && ((unsigned)xx < DS);
                const long cell = ok ? ((((long)b*DS + z)*DS + y)*DS + xx) : 0;
                const __nv_bfloat16* src =
                    (half ? inlo : inhi) + cell*CIN + kc*64 + seg*8;
                cpa16z(base + (uint32_t)half*16384u + swz((uint32_t)vox, (uint32_t)seg*16u),
                       src, ok);
            } else {                                  // B weight tiles
                const int f = flat - 2048;
                cpa16z(base + 32768u + (uint32_t)f*16u,
                       wA + (long)s*32768 + (long)f*16, true);
            }
        }
        cpa_commit();
    };

    stage_copy(0, 0);
    if (NT > 1) stage_copy(1, 1);

    int p = 0;
    for (int i = 0; i < NT; i++) {
        if (i < NT - 1) asm volatile("cp.async.wait_group 1;");
        else            asm volatile("cp.async.wait_group 0;");
        __syncthreads();

        if (i + 2 < NT) {
            int p2 = p + 2; if (p2 >= 3) p2 -= 3;
            stage_copy(i + 2, p2);
        }

        const uint32_t Ab = BUF + (uint32_t)p*65536u;
        const uint32_t Bb = Ab + 32768u;

        #pragma unroll
        for (int ks = 0; ks < 4; ks++) {
            const uint32_t colb = (uint32_t)(ks*16 + ((lane >> 4) & 1)*8) * 2u;
            uint32_t a_hi[2][4], a_lo[2][4];
            #pragma unroll
            for (int mf = 0; mf < 2; mf++) {
                const uint32_t row = (uint32_t)(wm*32 + mf*16 + (lane & 15));
                const uint32_t ad = Ab + swz(row, colb);
                ldsm4(a_hi[mf], ad);
                ldsm4(a_lo[mf], ad + 16384u);
            }
            uint32_t b_hi[8][2], b_lo[8][2];
            #pragma unroll
            for (int nf2 = 0; nf2 < 4; nf2++) {
                const uint32_t row = (uint32_t)(wn*64 + nf2*16 + (lane & 15));
                const uint32_t ad = Bb + swz(row, colb);
                uint32_t r4[4];
                ldsm4(r4, ad);
                b_hi[nf2*2][0] = r4[0]; b_hi[nf2*2+1][0] = r4[1];
                b_hi[nf2*2][1] = r4[2]; b_hi[nf2*2+1][1] = r4[3];
                ldsm4(r4, ad + 16384u);
                b_lo[nf2*2][0] = r4[0]; b_lo[nf2*2+1][0] = r4[1];
                b_lo[nf2*2][1] = r4[2]; b_lo[nf2*2+1][1] = r4[3];
            }
            // term-major: 16 independent accs per pass -> no RAW chains
            #pragma unroll
            for (int mf = 0; mf < 2; mf++)
                #pragma unroll
                for (int nf = 0; nf < 8; nf++)
                    mma16816(acc[mf][nf], a_hi[mf], b_hi[nf]);
            #pragma unroll
            for (int mf = 0; mf < 2; mf++)
                #pragma unroll
                for (int nf = 0; nf < 8; nf++)
                    mma16816(acc[mf][nf], a_hi[mf], b_lo[nf]);
            #pragma unroll
            for (int mf = 0; mf < 2; mf++)
                #pragma unroll
                for (int nf = 0; nf < 8; nf++)
                    mma16816(acc[mf][nf], a_lo[mf], b_hi[nf]);
        }
        p++; if (p == 3) p = 0;
    }
    __syncthreads();

    // ---- epilogue ----
    const int qr = lane >> 2;
    const int qc = lane & 3;

    #pragma unroll
    for (int mf = 0; mf < 2; mf++) {
        const int vox_lo = wm*32 + mf*16 + qr;
        const int vox_hi = vox_lo + 8;
        const long cell_lo = (((long)b*DS + dz)*DS + dy0 + (vox_lo >> 5))*DS + (vox_lo & 31);
        const long cell_hi = (((long)b*DS + dz)*DS + dy0 + (vox_hi >> 5))*DS + (vox_hi & 31);
        const float m_lo = m2[cell_lo];
        const float m_hi = m2[cell_hi];
        #pragma unroll
        for (int nf = 0; nf < 8; nf++) {
            const int co = wn*64 + nf*8 + qc*2;
            float b0 = bias[co], b1 = bias[co + 1];
            if (HAS_SKIP) { b0 += bias2[co]; b1 += bias2[co + 1]; }
            acc[mf][nf][0] = (acc[mf][nf][0] + b0) * m_lo;
            acc[mf][nf][1] = (acc[mf][nf][1] + b1) * m_lo;
            acc[mf][nf][2] = (acc[mf][nf][2] + b0) * m_hi;
            acc[mf][nf][3] = (acc[mf][nf][3] + b1) * m_hi;
        }
    }

    if (FUSE_LN) {
        float* ps = s_red;            // [128 vox][2 wn]
        float* qs = s_red + 256;
        #pragma unroll
        for (int mf = 0; mf < 2; mf++) {
            float S_lo = 0.f, Q_lo = 0.f, S_hi = 0.f, Q_hi = 0.f;
            #pragma unroll
            for (int nf = 0; nf < 8; nf++) {
                S_lo += acc[mf][nf][0] + acc[mf][nf][1];
                Q_lo += acc[mf][nf][0]*acc[mf][nf][0] + acc[mf][nf][1]*acc[mf][nf][1];
                S_hi += acc[mf][nf][2] + acc[mf][nf][3];
                Q_hi += acc[mf][nf][2]*acc[mf][nf][2] + acc[mf][nf][3]*acc[mf][nf][3];
            }
            #pragma unroll
            for (int o = 1; o < 4; o <<= 1) {
                S_lo += __shfl_xor_sync(0xffffffffu, S_lo, o);
                Q_lo += __shfl_xor_sync(0xffffffffu, Q_lo, o);
                S_hi += __shfl_xor_sync(0xffffffffu, S_hi, o);
                Q_hi += __shfl_xor_sync(0xffffffffu, Q_hi, o);
            }
            if (qc == 0) {
                const int vox_lo = wm*32 + mf*16 + qr;
                ps[vox_lo*2 + wn] = S_lo;  qs[vox_lo*2 + wn] = Q_lo;
                ps[(vox_lo + 8)*2 + wn] = S_hi;  qs[(vox_lo + 8)*2 + wn] = Q_hi;
            }
        }
        __syncthreads();
        #pragma unroll
        for (int mf = 0; mf < 2; mf++) {
            #pragma unroll
            for (int half = 0; half < 2; half++) {
                const int vox = wm*32 + mf*16 + qr + half*8;
                const long cell = (((long)b*DS + dz)*DS + dy0 + (vox >> 5))*DS + (vox & 31);
                const float m = m2[cell];
                const float S = ps[vox*2] + ps[vox*2 + 1];
                const float Q = qs[vox*2] + qs[vox*2 + 1];
                const float mu  = S * (1.f/128.f);
                const float var = Q * (1.f/128.f) - mu*mu;
                const float rsv = rsqrtf(var + 1e-6f);
                #pragma unroll
                for (int nf = 0; nf < 8; nf++) {
                    const int co = wn*64 + nf*8 + qc*2;
                    __nv_bfloat162 vh, vl;
                    #pragma unroll
                    for (int e = 0; e < 2; e++) {
                        const float lnv = (acc[mf][nf][half*2 + e] - mu) * rsv;
                        const float sil = (lnv / (1.f + __expf(-lnv))) * m;
                        const __nv_bfloat16 hi = __float2bfloat16(sil);
                        const __nv_bfloat16 lo = __float2bfloat16(sil - __bfloat162float(hi));
                        if (e == 0) { vh.x = hi; vl.x = lo; } else { vh.y = hi; vl.y = lo; }
                    }
                    *(__nv_bfloat162*)(outhi + cell*C2 + co) = vh;
                    *(__nv_bfloat162*)(outlo + cell*C2 + co) = vl;
                }
            }
        }
    } else {
        #pragma unroll
        for (int mf = 0; mf < 2; mf++) {
            #pragma unroll
            for (int half = 0; half < 2; half++) {
                const int vox = wm*32 + mf*16 + qr + half*8;
                const long cell = (((long)b*DS + dz)*DS + dy0 + (vox >> 5))*DS + (vox & 31);
                #pragma unroll
                for (int nf = 0; nf < 8; nf++) {
                    const int co = wn*64 + nf*8 + qc*2;
                    float2 v;
                    v.x = acc[mf][nf][half*2];
                    v.y = acc[mf][nf][half*2 + 1];
                    *(float2*)(outf + cell*C2 + co) = v;
                }
            }
        }
    }
}

// ---------------- launch ------------------------------------------------------
extern "C" void kernel_launch(void* const* d_in, const int* in_sizes, int n_in,
                              void* d_out, int out_size)
{
    const float* feats = (const float*)d_in[0];
    const void*  mask  = d_in[1];
    const float* gamma1= (const float*)d_in[2];
    const float* beta1 = (const float*)d_in[3];
    const float* w1    = (const float*)d_in[4];
    const float* b1    = (const float*)d_in[5];
    const float* w2    = (const float*)d_in[6];
    const float* b2    = (const float*)d_in[7];
    const float* wsk   = (const float*)d_in[8];
    const float* bsk   = (const float*)d_in[9];
    float* out = (float*)d_out;

    float *p_m2;
    __nv_bfloat16 *p_h1hi, *p_h1lo, *p_xhi, *p_xlo, *p_c1hi, *p_c1lo;
    unsigned char *p_wA1, *p_wA2;
    cudaGetSymbolAddress((void**)&p_m2,   g_m2);
    cudaGetSymbolAddress((void**)&p_h1hi, g_h1hi);
    cudaGetSymbolAddress((void**)&p_h1lo, g_h1lo);
    cudaGetSymbolAddress((void**)&p_xhi,  g_xhi);
    cudaGetSymbolAddress((void**)&p_xlo,  g_xlo);
    cudaGetSymbolAddress((void**)&p_c1hi, g_c1hi);
    cudaGetSymbolAddress((void**)&p_c1lo, g_c1lo);
    cudaGetSymbolAddress((void**)&p_wA1,  g_wA1);
    cudaGetSymbolAddress((void**)&p_wA2,  g_wA2);

    k_detect<<<1, 32>>>((const unsigned int*)mask, in_sizes[1] / 4);
    k_prep_w<<<432, 512>>>(w1, p_wA1, C1);
    k_prep_w<<<864, 512>>>(w2, p_wA2, C2);
    k_prep_skipw<<<16, 512>>>(wsk, p_wA2 + (long)54*32768);
    k_ln_ds<<<NCELL, 128>>>(feats, mask, gamma1, beta1);

    const size_t SMEMSZ = 1024 + 3*65536;             // align pad + 3 stage buffers
    dim3 gC(DS/4, DS, NB);                             // (dy strip, dz, b) = (8,32,4)

    cudaFuncSetAttribute(k_convmma<C1, true, false>,
                         cudaFuncAttributeMaxDynamicSharedMemorySize, (int)SMEMSZ);
    k_convmma<C1, true, false><<<gC, 256, SMEMSZ>>>(p_h1hi, p_h1lo, nullptr, nullptr,
                                                    p_wA1, b1, nullptr, p_m2,
                                                    nullptr, p_c1hi, p_c1lo);

    cudaFuncSetAttribute(k_convmma<C2, false, true>,
                         cudaFuncAttributeMaxDynamicSharedMemorySize, (int)SMEMSZ);
    k_convmma<C2, false, true><<<gC, 256, SMEMSZ>>>(p_c1hi, p_c1lo, p_xhi, p_xlo,
                                                    p_wA2, b2, bsk, p_m2,
                                                    out, nullptr, nullptr);
}

// round 16
// speedup vs baseline: 1.6483x; 1.0627x over previous
#include <cuda_runtime.h>
#include <cuda_bf16.h>
#include <cstdint>

#define NB 4
#define D0 64
#define C1 64
#define C2 128
#define DS 32
#define NCELL (NB*DS*DS*DS)   // 131072

// stage blob: A halo tile 17408 B (hi 8704 + lo 8704) + B 3x16384 B = 66560
#define STGB   66560u
#define A_LO   8704u
#define B_OFF  17408u
#define WBLOB  49152    // 3 kw x 16KB per weight stage

// ---------------- scratch (device globals) ----------------------------------
__device__ float          g_m2  [NCELL];
__device__ __nv_bfloat16  g_h1hi[NCELL*C1];
__device__ __nv_bfloat16  g_h1lo[NCELL*C1];
__device__ __nv_bfloat16  g_xhi [NCELL*C1];
__device__ __nv_bfloat16  g_xlo [NCELL*C1];
__device__ __nv_bfloat16  g_c1hi[NCELL*C2];
__device__ __nv_bfloat16  g_c1lo[NCELL*C2];
__device__ unsigned char  g_wA1[18*WBLOB];          // conv1: 9 taps x 2 kc
__device__ unsigned char  g_wA2[38*WBLOB];          // conv2: 36 + 2 skip stages
__device__ int            g_mask_mode;

// ---------------- helpers ----------------------------------------------------
__device__ __forceinline__ uint32_t smem_u32(const void* p){
    uint32_t a;
    asm("{ .reg .u64 t; cvta.to.shared.u64 t, %1; cvt.u32.u64 %0, t; }" : "=r"(a) : "l"(p));
    return a;
}
__device__ __forceinline__ void cpa16z(uint32_t dst, const void* src, bool ok){
    int sz = ok ? 16 : 0;
    asm volatile("cp.async.cg.shared.global [%0], [%1], 16, %2;" :: "r"(dst), "l"(src), "r"(sz));
}
__device__ __forceinline__ void cpa_commit(){ asm volatile("cp.async.commit_group;"); }

__device__ __forceinline__ void ldsm4(uint32_t* r, uint32_t addr){
    asm volatile("ldmatrix.sync.aligned.m8n8.x4.shared.b16 {%0,%1,%2,%3}, [%4];"
        : "=r"(r[0]), "=r"(r[1]), "=r"(r[2]), "=r"(r[3]) : "r"(addr));
}
__device__ __forceinline__ void mma16816(float* d, const uint32_t* a, const uint32_t* b){
    asm volatile("mma.sync.aligned.m16n8k16.row.col.f32.bf16.bf16.f32 "
        "{%0,%1,%2,%3}, {%4,%5,%6,%7}, {%8,%9}, {%0,%1,%2,%3};"
        : "+f"(d[0]), "+f"(d[1]), "+f"(d[2]), "+f"(d[3])
        : "r"(a[0]), "r"(a[1]), "r"(a[2]), "r"(a[3]), "r"(b[0]), "r"(b[1]));
}
// SW64 swizzle for 64B rows (32 ci x bf16)
__device__ __host__ __forceinline__ uint32_t swz64(uint32_t row, uint32_t bytecol){
    uint32_t off = row*64u + bytecol;
    return off ^ ((off >> 3) & 0x30u);
}

// ---------------- mask dtype detection ---------------------------------------
__global__ void k_detect(const unsigned int* __restrict__ m, int nwords)
{
    if (threadIdx.x == 0 && blockIdx.x == 0) {
        int mode = 0;
        for (int i = 0; i < nwords; i++) {
            unsigned w = m[i];
            if (w == 0u) continue;
            if (w == 1u)               mode = 0;
            else if (w == 0x3F800000u) mode = 0;
            else                       mode = 2;
            break;
        }
        g_mask_mode = mode;
    }
}
__device__ __forceinline__ bool mask_at(const void* m, long v, int mode)
{
    if (mode == 2) return ((const unsigned char*)m)[v] != 0;
    return ((const unsigned int*)m)[v] != 0u;
}

// ---------------- weight prep: kw-grouped SW64 stage blobs --------------------
// src w: [27 taps][CIN][128 co] fp32. stage s=(kd*3+kh)*(CIN/32)+kc:
// blob 48KB = kw*16KB, each [hi 8KB][lo 8KB], tile [128 co][32 ci] SW64.
__global__ void k_prep_w(const float* __restrict__ w, unsigned char* __restrict__ dst, int CIN)
{
    const int NKC32 = CIN >> 5;
    const int total = 27*CIN*128;
    for (int e = blockIdx.x*blockDim.x + threadIdx.x; e < total; e += gridDim.x*blockDim.x) {
        const int t   = e / (CIN*128);
        const int rem = e - t*(CIN*128);
        const int ci  = rem >> 7;
        const int co  = rem & 127;
        const float wv = w[e];
        const __nv_bfloat16 hi = __float2bfloat16(wv);
        const __nv_bfloat16 lo = __float2bfloat16(wv - __bfloat162float(hi));
        const int kd = t / 9;
        const int r9 = t - kd*9;
        const int kh = r9 / 3;
        const int kw = r9 - kh*3;
        const int kc = ci >> 5, cil = ci & 31;
        const int s  = (kd*3 + kh)*NKC32 + kc;
        unsigned char* base = dst + (long)s*WBLOB + kw*16384;
        const uint32_t off = swz64((uint32_t)co, (uint32_t)cil*2u);
        *(__nv_bfloat16*)(base + off)        = hi;
        *(__nv_bfloat16*)(base + 8192 + off) = lo;
    }
}

// skip weight: wsk [64 ci][128 co] -> stages 36+kc of g_wA2, kw=1 slot
__global__ void k_prep_skipw(const float* __restrict__ wsk, unsigned char* __restrict__ dst)
{
    const int e = blockIdx.x*blockDim.x + threadIdx.x;
    if (e < 64*128) {
        const int ci = e >> 7;
        const int co = e & 127;
        const float wv = wsk[e];
        const __nv_bfloat16 hi = __float2bfloat16(wv);
        const __nv_bfloat16 lo = __float2bfloat16(wv - __bfloat162float(hi));
        const int s = 36 + (ci >> 5);
        unsigned char* base = dst + (long)s*WBLOB + 16384;   // kw=1 slot
        const uint32_t off = swz64((uint32_t)co, (uint32_t)(ci & 31)*2u);
        *(__nv_bfloat16*)(base + off)        = hi;
        *(__nv_bfloat16*)(base + 8192 + off) = lo;
    }
}

// ---------------- K1: LN1+affine+SiLU+mask + 2x downsample -------------------
__global__ void __launch_bounds__(128)
k_ln_ds(const float* __restrict__ feats, const void* __restrict__ mask,
        const float* __restrict__ gamma, const float* __restrict__ beta)
{
    const int bid = blockIdx.x;
    const int dx = bid & 31, dy = (bid >> 5) & 31, dz = (bid >> 10) & 31, b = bid >> 15;
    const int tid  = threadIdx.x;
    const int lane = tid & 31;
    const int s    = ((tid >> 5) << 1) + (lane >> 4);
    const int ch4  = lane & 15;
    const int mode = g_mask_mode;

    __shared__ float sh_h[8*64];
    __shared__ float sh_x[8*64];
    __shared__ int   sh_c[8];

    const int z = 2*dz + (s >> 2);
    const int y = 2*dy + ((s >> 1) & 1);
    const int x = 2*dx + (s & 1);
    const long v = (((long)b*D0 + z)*D0 + y)*D0 + x;
    const bool act = mask_at(mask, v, mode);

    const float4 f = *(const float4*)(feats + v*C1 + ch4*4);
    float a = f.x + f.y + f.z + f.w;
    float q = f.x*f.x + f.y*f.y + f.z*f.z + f.w*f.w;
    #pragma unroll
    for (int o = 1; o < 16; o <<= 1) {
        a += __shfl_xor_sync(0xffffffffu, a, o);
        q += __shfl_xor_sync(0xffffffffu, q, o);
    }
    const float mu  = a * (1.f/64.f);
    const float var = q * (1.f/64.f) - mu*mu;
    const float rs  = rsqrtf(var + 1e-6f);

    const float4 g  = *(const float4*)(gamma + ch4*4);
    const float4 be = *(const float4*)(beta  + ch4*4);
    const float xv[4] = {f.x, f.y, f.z, f.w};
    const float gg[4] = {g.x, g.y, g.z, g.w};
    const float bb[4] = {be.x, be.y, be.z, be.w};
    float oh[4], ox[4];
    #pragma unroll
    for (int i = 0; i < 4; i++) {
        float hv = (xv[i] - mu)*rs*gg[i] + bb[i];
        hv = hv / (1.f + __expf(-hv));
        oh[i] = act ? hv    : 0.f;
        ox[i] = act ? xv[i] : 0.f;
    }
    *(float4*)(sh_h + s*64 + ch4*4) = *(const float4*)oh;
    *(float4*)(sh_x + s*64 + ch4*4) = *(const float4*)ox;
    if (ch4 == 0) sh_c[s] = act ? 1 : 0;
    __syncthreads();

    if (tid < 64) {
        float hs = 0.f, xs = 0.f;
        int cnt = 0;
        #pragma unroll
        for (int k = 0; k < 8; k++) {
            hs += sh_h[k*64 + tid];
            xs += sh_x[k*64 + tid];
            cnt += sh_c[k];
        }
        const float inv = 1.f / (float)max(cnt, 1);
        const float hv = hs * inv;
        const float xm = xs * inv;
        const __nv_bfloat16 hhi = __float2bfloat16(hv);
        const __nv_bfloat16 hlo = __float2bfloat16(hv - __bfloat162float(hhi));
        const __nv_bfloat16 xhi = __float2bfloat16(xm);
        const __nv_bfloat16 xlo = __float2bfloat16(xm - __bfloat162float(xhi));
        g_h1hi[(long)bid*C1 + tid] = hhi;
        g_h1lo[(long)bid*C1 + tid] = hlo;
        g_xhi [(long)bid*C1 + tid] = xhi;
        g_xlo [(long)bid*C1 + tid] = xlo;
        if (tid == 0) g_m2[bid] = (cnt > 0) ? 1.f : 0.f;
    }
}

// ---------------- conv via mma.sync (split-bf16 3-term) ----------------------
// Block 256 thr / 8 warps. Tile: 128 voxels (4 dy rows x 32 x) x 128 cout.
// Stage = (kd,kh,kc32): A halo tile [4 rows][34 x'][32 ci] shared across the
// 3 kw taps (ldmatrix row offset +kw); B = 3 kw weight tiles. Triple-buffered,
// one barrier per stage. Z-boundary kd blocks skipped. Skip GEMM = 2 extra
// stages using the kw=1 slot only.
template<int CIN, bool FUSE_LN, bool HAS_SKIP>
__global__ void __launch_bounds__(256, 1)
k_convmma(const __nv_bfloat16* __restrict__ inhi, const __nv_bfloat16* __restrict__ inlo,
          const __nv_bfloat16* __restrict__ skhi, const __nv_bfloat16* __restrict__ sklo,
          const unsigned char* __restrict__ wA, const float* __restrict__ bias,
          const float* __restrict__ bias2, const float* __restrict__ m2,
          float* __restrict__ outf,
          __nv_bfloat16* __restrict__ outhi, __nv_bfloat16* __restrict__ outlo)
{
    constexpr int NKC32 = CIN / 32;
    constexpr int NSS   = 9 * NKC32;       // full conv stage count

    extern __shared__ char smraw[];
    const uint32_t sb0 = smem_u32(smraw);
    const uint32_t BUF = (sb0 + 1023) & ~1023u;
    float* s_red = (float*)(smraw + (BUF - sb0));

    const int tid  = threadIdx.x;
    const int lane = tid & 31;
    const int w    = tid >> 5;
    const int wm   = w >> 1;          // 0..3 (dy row)
    const int wn   = w & 1;           // 0..1
    const int dy0  = blockIdx.x * 4;
    const int dz   = blockIdx.y;
    const int b    = blockIdx.z;

    const int s_begin = (dz == 0)    ? 3*NKC32 : 0;
    const int s_endc  = (dz == DS-1) ? 6*NKC32 : NSS;
    const int nconv   = s_endc - s_begin;
    const int NT      = nconv + (HAS_SKIP ? 2 : 0);

    float acc[2][8][4];
    #pragma unroll
    for (int mf = 0; mf < 2; mf++)
        #pragma unroll
        for (int nf = 0; nf < 8; nf++)
            #pragma unroll
            for (int k = 0; k < 4; k++) acc[mf][nf][k] = 0.f;

    // ---- stage copier ----
    auto stage_copy = [&](int i, int p){
        int s, kd, kh, kc, kwl;
        const __nv_bfloat16 *shi, *slo;
        int scin, nB;
        if (HAS_SKIP && i >= nconv) {
            kc = i - nconv; kd = 1; kh = 1; kwl = 1;
            s = NSS + kc; shi = skhi; slo = sklo; scin = C1; nB = 1024;
        } else {
            s = s_begin + i;
            const int t = s / NKC32; kc = s - t*NKC32;
            kd = t / 3; kh = t - kd*3; kwl = 0;
            shi = inhi; slo = inlo; scin = CIN; nB = 3072;
        }
        const int z = dz + kd - 1;
        const uint32_t base = BUF + (uint32_t)p*STGB;
        const int ntot = 1088 + nB;
        #pragma unroll
        for (int it = 0; it < 17; it++) {
            const int flat = tid + it*256;
            if (flat < 1088) {                       // A halo tile (hi, lo)
                const int half = (flat >= 544) ? 1 : 0;
                const int fa   = flat - half*544;
                const int vox  = fa >> 2;            // 0..135
                const int seg  = fa & 3;
                const int r    = vox / 34;
                const int xr   = vox - r*34;
                const int x    = xr - 1;
                const int y    = dy0 + r + kh - 1;
                const bool ok  = ((unsigned)y < DS) && ((unsigned)x < DS);
                const long cell = ok ? ((((long)b*DS + z)*DS + y)*DS + x) : 0;
                const __nv_bfloat16* src =
                    (half ? slo : shi) + cell*scin + kc*32 + seg*8;
                cpa16z(base + (uint32_t)half*A_LO + swz64((uint32_t)vox, (uint32_t)seg*16u),
                       src, ok);
            } else if (flat < ntot) {                // B weight blob (linear copy)
                const int f = flat - 1088;
                cpa16z(base + B_OFF + (uint32_t)kwl*16384u + (uint32_t)f*16u,
                       wA + (long)s*WBLOB + (long)kwl*16384 + (long)f*16, true);
            }
        }
        cpa_commit();
    };

    // ---- per-(ks,kw) MMA block ----
    auto do_kw = [&](int kw, uint32_t colb, uint32_t base){
        uint32_t a_hi[2][4], a_lo[2][4];
        #pragma unroll
        for (int mf = 0; mf < 2; mf++) {
            const uint32_t row = (uint32_t)(wm*34 + mf*16 + (lane & 15) + kw);
            const uint32_t ad = base + swz64(row, colb);
            ldsm4(a_hi[mf], ad);
            ldsm4(a_lo[mf], ad + A_LO);
        }
        const uint32_t Bslot = base + B_OFF + (uint32_t)kw*16384u;
        uint32_t b_hi[8][2], b_lo[8][2];
        #pragma unroll
        for (int nf2 = 0; nf2 < 4; nf2++) {
            const uint32_t row = (uint32_t)(wn*64 + nf2*16 + (lane & 15));
            const uint32_t ad = Bslot + swz64(row, colb);
            uint32_t r4[4];
            ldsm4(r4, ad);
            b_hi[nf2*2][0] = r4[0]; b_hi[nf2*2+1][0] = r4[1];
            b_hi[nf2*2][1] = r4[2]; b_hi[nf2*2+1][1] = r4[3];
            ldsm4(r4, ad + 8192u);
            b_lo[nf2*2][0] = r4[0]; b_lo[nf2*2+1][0] = r4[1];
            b_lo[nf2*2][1] = r4[2]; b_lo[nf2*2+1][1] = r4[3];
        }
        #pragma unroll
        for (int mf = 0; mf < 2; mf++)
            #pragma unroll
            for (int nf = 0; nf < 8; nf++)
                mma16816(acc[mf][nf], a_hi[mf], b_hi[nf]);
        #pragma unroll
        for (int mf = 0; mf < 2; mf++)
            #pragma unroll
            for (int nf = 0; nf < 8; nf++)
                mma16816(acc[mf][nf], a_hi[mf], b_lo[nf]);
        #pragma unroll
        for (int mf = 0; mf < 2; mf++)
            #pragma unroll
            for (int nf = 0; nf < 8; nf++)
                mma16816(acc[mf][nf], a_lo[mf], b_hi[nf]);
    };

    stage_copy(0, 0);
    if (NT > 1) stage_copy(1, 1);

    int p = 0;
    for (int i = 0; i < NT; i++) {
        if (i < NT - 1) asm volatile("cp.async.wait_group 1;");
        else            asm volatile("cp.async.wait_group 0;");
        __syncthreads();

        if (i + 2 < NT) {
            int p2 = p + 2; if (p2 >= 3) p2 -= 3;
            stage_copy(i + 2, p2);
        }

        const uint32_t base = BUF + (uint32_t)p*STGB;
        const bool isskip = HAS_SKIP && (i >= nconv);

        #pragma unroll
        for (int ks = 0; ks < 2; ks++) {
            const uint32_t colb = (uint32_t)(ks*32 + ((lane >> 4) & 1)*16);
            if (isskip) {
                do_kw(1, colb, base);
            } else {
                do_kw(0, colb, base);
                do_kw(1, colb, base);
                do_kw(2, colb, base);
            }
        }
        p++; if (p == 3) p = 0;
    }
    __syncthreads();

    // ---- epilogue ----
    const int qr = lane >> 2;
    const int qc = lane & 3;

    #pragma unroll
    for (int mf = 0; mf < 2; mf++) {
        const int vox_lo = wm*32 + mf*16 + qr;
        const int vox_hi = vox_lo + 8;
        const long cell_lo = (((long)b*DS + dz)*DS + dy0 + (vox_lo >> 5))*DS + (vox_lo & 31);
        const long cell_hi = (((long)b*DS + dz)*DS + dy0 + (vox_hi >> 5))*DS + (vox_hi & 31);
        const float m_lo = m2[cell_lo];
        const float m_hi = m2[cell_hi];
        #pragma unroll
        for (int nf = 0; nf < 8; nf++) {
            const int co = wn*64 + nf*8 + qc*2;
            float b0 = bias[co], b1 = bias[co + 1];
            if (HAS_SKIP) { b0 += bias2[co]; b1 += bias2[co + 1]; }
            acc[mf][nf][0] = (acc[mf][nf][0] + b0) * m_lo;
            acc[mf][nf][1] = (acc[mf][nf][1] + b1) * m_lo;
            acc[mf][nf][2] = (acc[mf][nf][2] + b0) * m_hi;
            acc[mf][nf][3] = (acc[mf][nf][3] + b1) * m_hi;
        }
    }

    if (FUSE_LN) {
        float* ps = s_red;            // [128 vox][2 wn]
        float* qs = s_red + 256;
        #pragma unroll
        for (int mf = 0; mf < 2; mf++) {
            float S_lo = 0.f, Q_lo = 0.f, S_hi = 0.f, Q_hi = 0.f;
            #pragma unroll
            for (int nf = 0; nf < 8; nf++) {
                S_lo += acc[mf][nf][0] + acc[mf][nf][1];
                Q_lo += acc[mf][nf][0]*acc[mf][nf][0] + acc[mf][nf][1]*acc[mf][nf][1];
                S_hi += acc[mf][nf][2] + acc[mf][nf][3];
                Q_hi += acc[mf][nf][2]*acc[mf][nf][2] + acc[mf][nf][3]*acc[mf][nf][3];
            }
            #pragma unroll
            for (int o = 1; o < 4; o <<= 1) {
                S_lo += __shfl_xor_sync(0xffffffffu, S_lo, o);
                Q_lo += __shfl_xor_sync(0xffffffffu, Q_lo, o);
                S_hi += __shfl_xor_sync(0xffffffffu, S_hi, o);
                Q_hi += __shfl_xor_sync(0xffffffffu, Q_hi, o);
            }
            if (qc == 0) {
                const int vox_lo = wm*32 + mf*16 + qr;
                ps[vox_lo*2 + wn] = S_lo;  qs[vox_lo*2 + wn] = Q_lo;
                ps[(vox_lo + 8)*2 + wn] = S_hi;  qs[(vox_lo + 8)*2 + wn] = Q_hi;
            }
        }
        __syncthreads();
        #pragma unroll
        for (int mf = 0; mf < 2; mf++) {
            #pragma unroll
            for (int half = 0; half < 2; half++) {
                const int vox = wm*32 + mf*16 + qr + half*8;
                const long cell = (((long)b*DS + dz)*DS + dy0 + (vox >> 5))*DS + (vox & 31);
                const float m = m2[cell];
                const float S = ps[vox*2] + ps[vox*2 + 1];
                const float Q = qs[vox*2] + qs[vox*2 + 1];
                const float mu  = S * (1.f/128.f);
                const float var = Q * (1.f/128.f) - mu*mu;
                const float rsv = rsqrtf(var + 1e-6f);
                #pragma unroll
                for (int nf = 0; nf < 8; nf++) {
                    const int co = wn*64 + nf*8 + qc*2;
                    __nv_bfloat162 vh, vl;
                    #pragma unroll
                    for (int e = 0; e < 2; e++) {
                        const float lnv = (acc[mf][nf][half*2 + e] - mu) * rsv;
                        const float sil = (lnv / (1.f + __expf(-lnv))) * m;
                        const __nv_bfloat16 hi = __float2bfloat16(sil);
                        const __nv_bfloat16 lo = __float2bfloat16(sil - __bfloat162float(hi));
                        if (e == 0) { vh.x = hi; vl.x = lo; } else { vh.y = hi; vl.y = lo; }
                    }
                    *(__nv_bfloat162*)(outhi + cell*C2 + co) = vh;
                    *(__nv_bfloat162*)(outlo + cell*C2 + co) = vl;
                }
            }
        }
    } else {
        #pragma unroll
        for (int mf = 0; mf < 2; mf++) {
            #pragma unroll
            for (int half = 0; half < 2; half++) {
                const int vox = wm*32 + mf*16 + qr + half*8;
                const long cell = (((long)b*DS + dz)*DS + dy0 + (vox >> 5))*DS + (vox & 31);
                #pragma unroll
                for (int nf = 0; nf < 8; nf++) {
                    const int co = wn*64 + nf*8 + qc*2;
                    float2 v;
                    v.x = acc[mf][nf][half*2];
                    v.y = acc[mf][nf][half*2 + 1];
                    *(float2*)(outf + cell*C2 + co) = v;
                }
            }
        }
    }
}

// ---------------- launch ------------------------------------------------------
extern "C" void kernel_launch(void* const* d_in, const int* in_sizes, int n_in,
                              void* d_out, int out_size)
{
    const float* feats = (const float*)d_in[0];
    const void*  mask  = d_in[1];
    const float* gamma1= (const float*)d_in[2];
    const float* beta1 = (const float*)d_in[3];
    const float* w1    = (const float*)d_in[4];
    const float* b1    = (const float*)d_in[5];
    const float* w2    = (const float*)d_in[6];
    const float* b2    = (const float*)d_in[7];
    const float* wsk   = (const float*)d_in[8];
    const float* bsk   = (const float*)d_in[9];
    float* out = (float*)d_out;

    float *p_m2;
    __nv_bfloat16 *p_h1hi, *p_h1lo, *p_xhi, *p_xlo, *p_c1hi, *p_c1lo;
    unsigned char *p_wA1, *p_wA2;
    cudaGetSymbolAddress((void**)&p_m2,   g_m2);
    cudaGetSymbolAddress((void**)&p_h1hi, g_h1hi);
    cudaGetSymbolAddress((void**)&p_h1lo, g_h1lo);
    cudaGetSymbolAddress((void**)&p_xhi,  g_xhi);
    cudaGetSymbolAddress((void**)&p_xlo,  g_xlo);
    cudaGetSymbolAddress((void**)&p_c1hi, g_c1hi);
    cudaGetSymbolAddress((void**)&p_c1lo, g_c1lo);
    cudaGetSymbolAddress((void**)&p_wA1,  g_wA1);
    cudaGetSymbolAddress((void**)&p_wA2,  g_wA2);

    k_detect<<<1, 32>>>((const unsigned int*)mask, in_sizes[1] / 4);
    k_prep_w<<<432, 512>>>(w1, p_wA1, C1);
    k_prep_w<<<864, 512>>>(w2, p_wA2, C2);
    k_prep_skipw<<<16, 512>>>(wsk, p_wA2);
    k_ln_ds<<<NCELL, 128>>>(feats, mask, gamma1, beta1);

    const size_t SMEMSZ = 1024 + 3*STGB;              // 1024 align pad + 3 stages
    dim3 gC(DS/4, DS, NB);                             // (dy strip, dz, b) = (8,32,4)

    cudaFuncSetAttribute(k_convmma<C1, true, false>,
                         cudaFuncAttributeMaxDynamicSharedMemorySize, (int)SMEMSZ);
    k_convmma<C1, true, false><<<gC, 256, SMEMSZ>>>(p_h1hi, p_h1lo, nullptr, nullptr,
                                                    p_wA1, b1, nullptr, p_m2,
                                                    nullptr, p_c1hi, p_c1lo);

    cudaFuncSetAttribute(k_convmma<C2, false, true>,
                         cudaFuncAttributeMaxDynamicSharedMemorySize, (int)SMEMSZ);
    k_convmma<C2, false, true><<<gC, 256, SMEMSZ>>>(p_c1hi, p_c1lo, p_xhi, p_xlo,
                                                    p_wA2, b2, bsk, p_m2,
                                                    out, nullptr, nullptr);
}

// round 17
// speedup vs baseline: 1.6557x; 1.0045x over previous
#include <cuda_runtime.h>
#include <cuda_bf16.h>
#include <cstdint>

#define NB 4
#define D0 64
#define C1 64
#define C2 128
#define DS 32
#define NCELL (NB*DS*DS*DS)   // 131072

// stage blob: A halo tile 17408 B (hi 8704 + lo 8704) + B 3x16384 B = 66560
#define STGB   66560u
#define A_LO   8704u
#define B_OFF  17408u
#define WBLOB  49152    // 3 kw x 16KB per weight stage

// ---------------- scratch (device globals) ----------------------------------
__device__ float          g_m2  [NCELL];
__device__ __nv_bfloat16  g_h1hi[NCELL*C1];
__device__ __nv_bfloat16  g_h1lo[NCELL*C1];
__device__ __nv_bfloat16  g_xhi [NCELL*C1];
__device__ __nv_bfloat16  g_xlo [NCELL*C1];
__device__ __nv_bfloat16  g_c1hi[NCELL*C2];
__device__ __nv_bfloat16  g_c1lo[NCELL*C2];
__device__ unsigned char  g_wA1[18*WBLOB];          // conv1: 9 taps x 2 kc
__device__ unsigned char  g_wA2[38*WBLOB];          // conv2: 36 + 2 skip stages
__device__ int            g_mask_mode;

// ---------------- helpers ----------------------------------------------------
__device__ __forceinline__ uint32_t smem_u32(const void* p){
    uint32_t a;
    asm("{ .reg .u64 t; cvta.to.shared.u64 t, %1; cvt.u32.u64 %0, t; }" : "=r"(a) : "l"(p));
    return a;
}
__device__ __forceinline__ void cpa16z(uint32_t dst, const void* src, bool ok){
    int sz = ok ? 16 : 0;
    asm volatile("cp.async.cg.shared.global [%0], [%1], 16, %2;" :: "r"(dst), "l"(src), "r"(sz));
}
__device__ __forceinline__ void cpa_commit(){ asm volatile("cp.async.commit_group;"); }

__device__ __forceinline__ void ldsm4(uint32_t* r, uint32_t addr){
    asm volatile("ldmatrix.sync.aligned.m8n8.x4.shared.b16 {%0,%1,%2,%3}, [%4];"
        : "=r"(r[0]), "=r"(r[1]), "=r"(r[2]), "=r"(r[3]) : "r"(addr));
}
__device__ __forceinline__ void mma16816(float* d, const uint32_t* a, const uint32_t* b){
    asm volatile("mma.sync.aligned.m16n8k16.row.col.f32.bf16.bf16.f32 "
        "{%0,%1,%2,%3}, {%4,%5,%6,%7}, {%8,%9}, {%0,%1,%2,%3};"
        : "+f"(d[0]), "+f"(d[1]), "+f"(d[2]), "+f"(d[3])
        : "r"(a[0]), "r"(a[1]), "r"(a[2]), "r"(a[3]), "r"(b[0]), "r"(b[1]));
}
// SW64 swizzle for 64B rows (32 ci x bf16)
__device__ __host__ __forceinline__ uint32_t swz64(uint32_t row, uint32_t bytecol){
    uint32_t off = row*64u + bytecol;
    return off ^ ((off >> 3) & 0x30u);
}

// ---------------- mask dtype detection ---------------------------------------
__global__ void k_detect(const unsigned int* __restrict__ m, int nwords)
{
    if (threadIdx.x == 0 && blockIdx.x == 0) {
        int mode = 0;
        for (int i = 0; i < nwords; i++) {
            unsigned w = m[i];
            if (w == 0u) continue;
            if (w == 1u)               mode = 0;
            else if (w == 0x3F800000u) mode = 0;
            else                       mode = 2;
            break;
        }
        g_mask_mode = mode;
    }
}
__device__ __forceinline__ bool mask_at(const void* m, long v, int mode)
{
    if (mode == 2) return ((const unsigned char*)m)[v] != 0;
    return ((const unsigned int*)m)[v] != 0u;
}

// ---------------- weight prep: kw-grouped SW64 stage blobs --------------------
__global__ void k_prep_w(const float* __restrict__ w, unsigned char* __restrict__ dst, int CIN)
{
    const int NKC32 = CIN >> 5;
    const int total = 27*CIN*128;
    for (int e = blockIdx.x*blockDim.x + threadIdx.x; e < total; e += gridDim.x*blockDim.x) {
        const int t   = e / (CIN*128);
        const int rem = e - t*(CIN*128);
        const int ci  = rem >> 7;
        const int co  = rem & 127;
        const float wv = w[e];
        const __nv_bfloat16 hi = __float2bfloat16(wv);
        const __nv_bfloat16 lo = __float2bfloat16(wv - __bfloat162float(hi));
        const int kd = t / 9;
        const int r9 = t - kd*9;
        const int kh = r9 / 3;
        const int kw = r9 - kh*3;
        const int kc = ci >> 5, cil = ci & 31;
        const int s  = (kd*3 + kh)*NKC32 + kc;
        unsigned char* base = dst + (long)s*WBLOB + kw*16384;
        const uint32_t off = swz64((uint32_t)co, (uint32_t)cil*2u);
        *(__nv_bfloat16*)(base + off)        = hi;
        *(__nv_bfloat16*)(base + 8192 + off) = lo;
    }
}

// skip weight: wsk [64 ci][128 co] -> stages 36+kc of g_wA2, kw=1 slot
__global__ void k_prep_skipw(const float* __restrict__ wsk, unsigned char* __restrict__ dst)
{
    const int e = blockIdx.x*blockDim.x + threadIdx.x;
    if (e < 64*128) {
        const int ci = e >> 7;
        const int co = e & 127;
        const float wv = wsk[e];
        const __nv_bfloat16 hi = __float2bfloat16(wv);
        const __nv_bfloat16 lo = __float2bfloat16(wv - __bfloat162float(hi));
        const int s = 36 + (ci >> 5);
        unsigned char* base = dst + (long)s*WBLOB + 16384;   // kw=1 slot
        const uint32_t off = swz64((uint32_t)co, (uint32_t)(ci & 31)*2u);
        *(__nv_bfloat16*)(base + off)        = hi;
        *(__nv_bfloat16*)(base + 8192 + off) = lo;
    }
}

// ---------------- K1: LN1+affine+SiLU+mask + 2x downsample -------------------
__global__ void __launch_bounds__(128)
k_ln_ds(const float* __restrict__ feats, const void* __restrict__ mask,
        const float* __restrict__ gamma, const float* __restrict__ beta)
{
    const int bid = blockIdx.x;
    const int dx = bid & 31, dy = (bid >> 5) & 31, dz = (bid >> 10) & 31, b = bid >> 15;
    const int tid  = threadIdx.x;
    const int lane = tid & 31;
    const int s    = ((tid >> 5) << 1) + (lane >> 4);
    const int ch4  = lane & 15;
    const int mode = g_mask_mode;

    __shared__ float sh_h[8*64];
    __shared__ float sh_x[8*64];
    __shared__ int   sh_c[8];

    const int z = 2*dz + (s >> 2);
    const int y = 2*dy + ((s >> 1) & 1);
    const int x = 2*dx + (s & 1);
    const long v = (((long)b*D0 + z)*D0 + y)*D0 + x;
    const bool act = mask_at(mask, v, mode);

    const float4 f = *(const float4*)(feats + v*C1 + ch4*4);
    float a = f.x + f.y + f.z + f.w;
    float q = f.x*f.x + f.y*f.y + f.z*f.z + f.w*f.w;
    #pragma unroll
    for (int o = 1; o < 16; o <<= 1) {
        a += __shfl_xor_sync(0xffffffffu, a, o);
        q += __shfl_xor_sync(0xffffffffu, q, o);
    }
    const float mu  = a * (1.f/64.f);
    const float var = q * (1.f/64.f) - mu*mu;
    const float rs  = rsqrtf(var + 1e-6f);

    const float4 g  = *(const float4*)(gamma + ch4*4);
    const float4 be = *(const float4*)(beta  + ch4*4);
    const float xv[4] = {f.x, f.y, f.z, f.w};
    const float gg[4] = {g.x, g.y, g.z, g.w};
    const float bb[4] = {be.x, be.y, be.z, be.w};
    float oh[4], ox[4];
    #pragma unroll
    for (int i = 0; i < 4; i++) {
        float hv = (xv[i] - mu)*rs*gg[i] + bb[i];
        hv = hv / (1.f + __expf(-hv));
        oh[i] = act ? hv    : 0.f;
        ox[i] = act ? xv[i] : 0.f;
    }
    *(float4*)(sh_h + s*64 + ch4*4) = *(const float4*)oh;
    *(float4*)(sh_x + s*64 + ch4*4) = *(const float4*)ox;
    if (ch4 == 0) sh_c[s] = act ? 1 : 0;
    __syncthreads();

    if (tid < 64) {
        float hs = 0.f, xs = 0.f;
        int cnt = 0;
        #pragma unroll
        for (int k = 0; k < 8; k++) {
            hs += sh_h[k*64 + tid];
            xs += sh_x[k*64 + tid];
            cnt += sh_c[k];
        }
        const float inv = 1.f / (float)max(cnt, 1);
        const float hv = hs * inv;
        const float xm = xs * inv;
        const __nv_bfloat16 hhi = __float2bfloat16(hv);
        const __nv_bfloat16 hlo = __float2bfloat16(hv - __bfloat162float(hhi));
        const __nv_bfloat16 xhi = __float2bfloat16(xm);
        const __nv_bfloat16 xlo = __float2bfloat16(xm - __bfloat162float(xhi));
        g_h1hi[(long)bid*C1 + tid] = hhi;
        g_h1lo[(long)bid*C1 + tid] = hlo;
        g_xhi [(long)bid*C1 + tid] = xhi;
        g_xlo [(long)bid*C1 + tid] = xlo;
        if (tid == 0) g_m2[bid] = (cnt > 0) ? 1.f : 0.f;
    }
}

// ---------------- conv via mma.sync (split-bf16 3-term) ----------------------
// Block 512 thr / 16 warps. Tile: 128 voxels (4 dy rows x 32 x) x 128 cout.
// Warp (wm 0..3, wn 0..3): 32 vox x 32 co; frags 2 m x 4 n of m16n8k16.
// Stage = (kd,kh,kc32), A halo tile shared across the 3 kw taps.
template<int CIN, bool FUSE_LN, bool HAS_SKIP>
__global__ void __launch_bounds__(512, 1)
k_convmma(const __nv_bfloat16* __restrict__ inhi, const __nv_bfloat16* __restrict__ inlo,
          const __nv_bfloat16* __restrict__ skhi, const __nv_bfloat16* __restrict__ sklo,
          const unsigned char* __restrict__ wA, const float* __restrict__ bias,
          const float* __restrict__ bias2, const float* __restrict__ m2,
          float* __restrict__ outf,
          __nv_bfloat16* __restrict__ outhi, __nv_bfloat16* __restrict__ outlo)
{
    constexpr int NKC32 = CIN / 32;
    constexpr int NSS   = 9 * NKC32;

    extern __shared__ char smraw[];
    const uint32_t sb0 = smem_u32(smraw);
    const uint32_t BUF = (sb0 + 1023) & ~1023u;
    float* s_red = (float*)(smraw + (BUF - sb0));

    const int tid  = threadIdx.x;
    const int lane = tid & 31;
    const int w    = tid >> 5;
    const int wm   = w >> 2;          // 0..3 (dy row)
    const int wn   = w & 3;           // 0..3 (32-co group)
    const int dy0  = blockIdx.x * 4;
    const int dz   = blockIdx.y;
    const int b    = blockIdx.z;

    const int s_begin = (dz == 0)    ? 3*NKC32 : 0;
    const int s_endc  = (dz == DS-1) ? 6*NKC32 : NSS;
    const int nconv   = s_endc - s_begin;
    const int NT      = nconv + (HAS_SKIP ? 2 : 0);

    float acc[2][4][4];
    #pragma unroll
    for (int mf = 0; mf < 2; mf++)
        #pragma unroll
        for (int nf = 0; nf < 4; nf++)
            #pragma unroll
            for (int k = 0; k < 4; k++) acc[mf][nf][k] = 0.f;

    // ---- stage copier (512-thread stride) ----
    auto stage_copy = [&](int i, int p){
        int s, kd, kh, kc, kwl;
        const __nv_bfloat16 *shi, *slo;
        int scin, nB;
        if (HAS_SKIP && i >= nconv) {
            kc = i - nconv; kd = 1; kh = 1; kwl = 1;
            s = NSS + kc; shi = skhi; slo = sklo; scin = C1; nB = 1024;
        } else {
            s = s_begin + i;
            const int t = s / NKC32; kc = s - t*NKC32;
            kd = t / 3; kh = t - kd*3; kwl = 0;
            shi = inhi; slo = inlo; scin = CIN; nB = 3072;
        }
        const int z = dz + kd - 1;
        const uint32_t base = BUF + (uint32_t)p*STGB;
        const int ntot = 1088 + nB;
        #pragma unroll
        for (int it = 0; it < 9; it++) {
            const int flat = tid + it*512;
            if (flat < 1088) {                       // A halo tile (hi, lo)
                const int half = (flat >= 544) ? 1 : 0;
                const int fa   = flat - half*544;
                const int vox  = fa >> 2;            // 0..135
                const int seg  = fa & 3;
                const int r    = vox / 34;
                const int xr   = vox - r*34;
                const int x    = xr - 1;
                const int y    = dy0 + r + kh - 1;
                const bool ok  = ((unsigned)y < DS) && ((unsigned)x < DS);
                const long cell = ok ? ((((long)b*DS + z)*DS + y)*DS + x) : 0;
                const __nv_bfloat16* src =
                    (half ? slo : shi) + cell*scin + kc*32 + seg*8;
                cpa16z(base + (uint32_t)half*A_LO + swz64((uint32_t)vox, (uint32_t)seg*16u),
                       src, ok);
            } else if (flat < ntot) {                // B weight blob (linear copy)
                const int f = flat - 1088;
                cpa16z(base + B_OFF + (uint32_t)kwl*16384u + (uint32_t)f*16u,
                       wA + (long)s*WBLOB + (long)kwl*16384 + (long)f*16, true);
            }
        }
        cpa_commit();
    };

    // ---- per-(ks,kw) MMA block ----
    auto do_kw = [&](int kw, uint32_t colb, uint32_t base){
        uint32_t a_hi[2][4], a_lo[2][4];
        #pragma unroll
        for (int mf = 0; mf < 2; mf++) {
            const uint32_t row = (uint32_t)(wm*34 + mf*16 + (lane & 15) + kw);
            const uint32_t ad = base + swz64(row, colb);
            ldsm4(a_hi[mf], ad);
            ldsm4(a_lo[mf], ad + A_LO);
        }
        const uint32_t Bslot = base + B_OFF + (uint32_t)kw*16384u;
        uint32_t b_hi[4][2], b_lo[4][2];
        #pragma unroll
        for (int nf2 = 0; nf2 < 2; nf2++) {
            const uint32_t row = (uint32_t)(wn*32 + nf2*16 + (lane & 15));
            const uint32_t ad = Bslot + swz64(row, colb);
            uint32_t r4[4];
            ldsm4(r4, ad);
            b_hi[nf2*2][0] = r4[0]; b_hi[nf2*2+1][0] = r4[1];
            b_hi[nf2*2][1] = r4[2]; b_hi[nf2*2+1][1] = r4[3];
            ldsm4(r4, ad + 8192u);
            b_lo[nf2*2][0] = r4[0]; b_lo[nf2*2+1][0] = r4[1];
            b_lo[nf2*2][1] = r4[2]; b_lo[nf2*2+1][1] = r4[3];
        }
        #pragma unroll
        for (int mf = 0; mf < 2; mf++)
            #pragma unroll
            for (int nf = 0; nf < 4; nf++)
                mma16816(acc[mf][nf], a_hi[mf], b_hi[nf]);
        #pragma unroll
        for (int mf = 0; mf < 2; mf++)
            #pragma unroll
            for (int nf = 0; nf < 4; nf++)
                mma16816(acc[mf][nf], a_hi[mf], b_lo[nf]);
        #pragma unroll
        for (int mf = 0; mf < 2; mf++)
            #pragma unroll
            for (int nf = 0; nf < 4; nf++)
                mma16816(acc[mf][nf], a_lo[mf], b_hi[nf]);
    };

    stage_copy(0, 0);
    if (NT > 1) stage_copy(1, 1);

    int p = 0;
    for (int i = 0; i < NT; i++) {
        if (i < NT - 1) asm volatile("cp.async.wait_group 1;");
        else            asm volatile("cp.async.wait_group 0;");
        __syncthreads();

        if (i + 2 < NT) {
            int p2 = p + 2; if (p2 >= 3) p2 -= 3;
            stage_copy(i + 2, p2);
        }

        const uint32_t base = BUF + (uint32_t)p*STGB;
        const bool isskip = HAS_SKIP && (i >= nconv);

        #pragma unroll
        for (int ks = 0; ks < 2; ks++) {
            const uint32_t colb = (uint32_t)(ks*32 + ((lane >> 4) & 1)*16);
            if (isskip) {
                do_kw(1, colb, base);
            } else {
                do_kw(0, colb, base);
                do_kw(1, colb, base);
                do_kw(2, colb, base);
            }
        }
        p++; if (p == 3) p = 0;
    }
    __syncthreads();

    // ---- epilogue ----
    const int qr = lane >> 2;
    const int qc = lane & 3;

    #pragma unroll
    for (int mf = 0; mf < 2; mf++) {
        const int vox_lo = wm*32 + mf*16 + qr;
        const int vox_hi = vox_lo + 8;
        const long cell_lo = (((long)b*DS + dz)*DS + dy0 + (vox_lo >> 5))*DS + (vox_lo & 31);
        const long cell_hi = (((long)b*DS + dz)*DS + dy0 + (vox_hi >> 5))*DS + (vox_hi & 31);
        const float m_lo = m2[cell_lo];
        const float m_hi = m2[cell_hi];
        #pragma unroll
        for (int nf = 0; nf < 4; nf++) {
            const int co = wn*32 + nf*8 + qc*2;
            float b0 = bias[co], b1 = bias[co + 1];
            if (HAS_SKIP) { b0 += bias2[co]; b1 += bias2[co + 1]; }
            acc[mf][nf][0] = (acc[mf][nf][0] + b0) * m_lo;
            acc[mf][nf][1] = (acc[mf][nf][1] + b1) * m_lo;
            acc[mf][nf][2] = (acc[mf][nf][2] + b0) * m_hi;
            acc[mf][nf][3] = (acc[mf][nf][3] + b1) * m_hi;
        }
    }

    if (FUSE_LN) {
        float* ps = s_red;            // [128 vox][4 wn]
        float* qs = s_red + 512;
        #pragma unroll
        for (int mf = 0; mf < 2; mf++) {
            float S_lo = 0.f, Q_lo = 0.f, S_hi = 0.f, Q_hi = 0.f;
            #pragma unroll
            for (int nf = 0; nf < 4; nf++) {
                S_lo += acc[mf][nf][0] + acc[mf][nf][1];
                Q_lo += acc[mf][nf][0]*acc[mf][nf][0] + acc[mf][nf][1]*acc[mf][nf][1];
                S_hi += acc[mf][nf][2] + acc[mf][nf][3];
                Q_hi += acc[mf][nf][2]*acc[mf][nf][2] + acc[mf][nf][3]*acc[mf][nf][3];
            }
            #pragma unroll
            for (int o = 1; o < 4; o <<= 1) {
                S_lo += __shfl_xor_sync(0xffffffffu, S_lo, o);
                Q_lo += __shfl_xor_sync(0xffffffffu, Q_lo, o);
                S_hi += __shfl_xor_sync(0xffffffffu, S_hi, o);
                Q_hi += __shfl_xor_sync(0xffffffffu, Q_hi, o);
            }
            if (qc == 0) {
                const int vox_lo = wm*32 + mf*16 + qr;
                ps[vox_lo*4 + wn] = S_lo;  qs[vox_lo*4 + wn] = Q_lo;
                ps[(vox_lo + 8)*4 + wn] = S_hi;  qs[(vox_lo + 8)*4 + wn] = Q_hi;
            }
        }
        __syncthreads();
        #pragma unroll
        for (int mf = 0; mf < 2; mf++) {
            #pragma unroll
            for (int half = 0; half < 2; half++) {
                const int vox = wm*32 + mf*16 + qr + half*8;
                const long cell = (((long)b*DS + dz)*DS + dy0 + (vox >> 5))*DS + (vox & 31);
                const float m = m2[cell];
                const float S = ps[vox*4] + ps[vox*4+1] + ps[vox*4+2] + ps[vox*4+3];
                const float Q = qs[vox*4] + qs[vox*4+1] + qs[vox*4+2] + qs[vox*4+3];
                const float mu  = S * (1.f/128.f);
                const float var = Q * (1.f/128.f) - mu*mu;
                const float rsv = rsqrtf(var + 1e-6f);
                #pragma unroll
                for (int nf = 0; nf < 4; nf++) {
                    const int co = wn*32 + nf*8 + qc*2;
                    __nv_bfloat162 vh, vl;
                    #pragma unroll
                    for (int e = 0; e < 2; e++) {
                        const float lnv = (acc[mf][nf][half*2 + e] - mu) * rsv;
                        const float sil = (lnv / (1.f + __expf(-lnv))) * m;
                        const __nv_bfloat16 hi = __float2bfloat16(sil);
                        const __nv_bfloat16 lo = __float2bfloat16(sil - __bfloat162float(hi));
                        if (e == 0) { vh.x = hi; vl.x = lo; } else { vh.y = hi; vl.y = lo; }
                    }
                    *(__nv_bfloat162*)(outhi + cell*C2 + co) = vh;
                    *(__nv_bfloat162*)(outlo + cell*C2 + co) = vl;
                }
            }
        }
    } else {
        #pragma unroll
        for (int mf = 0; mf < 2; mf++) {
            #pragma unroll
            for (int half = 0; half < 2; half++) {
                const int vox = wm*32 + mf*16 + qr + half*8;
                const long cell = (((long)b*DS + dz)*DS + dy0 + (vox >> 5))*DS + (vox & 31);
                #pragma unroll
                for (int nf = 0; nf < 4; nf++) {
                    const int co = wn*32 + nf*8 + qc*2;
                    float2 v;
                    v.x = acc[mf][nf][half*2];
                    v.y = acc[mf][nf][half*2 + 1];
                    *(float2*)(outf + cell*C2 + co) = v;
                }
            }
        }
    }
}

// ---------------- launch ------------------------------------------------------
extern "C" void kernel_launch(void* const* d_in, const int* in_sizes, int n_in,
                              void* d_out, int out_size)
{
    const float* feats = (const float*)d_in[0];
    const void*  mask  = d_in[1];
    const float* gamma1= (const float*)d_in[2];
    const float* beta1 = (const float*)d_in[3];
    const float* w1    = (const float*)d_in[4];
    const float* b1    = (const float*)d_in[5];
    const float* w2    = (const float*)d_in[6];
    const float* b2    = (const float*)d_in[7];
    const float* wsk   = (const float*)d_in[8];
    const float* bsk   = (const float*)d_in[9];
    float* out = (float*)d_out;

    float *p_m2;
    __nv_bfloat16 *p_h1hi, *p_h1lo, *p_xhi, *p_xlo, *p_c1hi, *p_c1lo;
    unsigned char *p_wA1, *p_wA2;
    cudaGetSymbolAddress((void**)&p_m2,   g_m2);
    cudaGetSymbolAddress((void**)&p_h1hi, g_h1hi);
    cudaGetSymbolAddress((void**)&p_h1lo, g_h1lo);
    cudaGetSymbolAddress((void**)&p_xhi,  g_xhi);
    cudaGetSymbolAddress((void**)&p_xlo,  g_xlo);
    cudaGetSymbolAddress((void**)&p_c1hi, g_c1hi);
    cudaGetSymbolAddress((void**)&p_c1lo, g_c1lo);
    cudaGetSymbolAddress((void**)&p_wA1,  g_wA1);
    cudaGetSymbolAddress((void**)&p_wA2,  g_wA2);

    k_detect<<<1, 32>>>((const unsigned int*)mask, in_sizes[1] / 4);
    k_prep_w<<<432, 512>>>(w1, p_wA1, C1);
    k_prep_w<<<864, 512>>>(w2, p_wA2, C2);
    k_prep_skipw<<<16, 512>>>(wsk, p_wA2);
    k_ln_ds<<<NCELL, 128>>>(feats, mask, gamma1, beta1);

    const size_t SMEMSZ = 1024 + 3*STGB;              // 1024 align pad + 3 stages
    dim3 gC(DS/4, DS, NB);                             // (dy strip, dz, b) = (8,32,4)

    cudaFuncSetAttribute(k_convmma<C1, true, false>,
                         cudaFuncAttributeMaxDynamicSharedMemorySize, (int)SMEMSZ);
    k_convmma<C1, true, false><<<gC, 512, SMEMSZ>>>(p_h1hi, p_h1lo, nullptr, nullptr,
                                                    p_wA1, b1, nullptr, p_m2,
                                                    nullptr, p_c1hi, p_c1lo);

    cudaFuncSetAttribute(k_convmma<C2, false, true>,
                         cudaFuncAttributeMaxDynamicSharedMemorySize, (int)SMEMSZ);
    k_convmma<C2, false, true><<<gC, 512, SMEMSZ>>>(p_c1hi, p_c1lo, p_xhi, p_xlo,
                                                    p_wA2, b2, bsk, p_m2,
                                                    out, nullptr, nullptr);
}